// round 1
// baseline (speedup 1.0000x reference)
#include <cuda_runtime.h>
#include <math.h>

// Cox partial-likelihood loss, N = 8192.
//   risk_sum[i] = sum_j exp(theta_j) * (t_j >= t_i)
//   loss = -(1/N) * sum_i (theta_i - log(risk_sum[i])) * censor_i
//
// Inputs (metadata order):
//   d_in[0]: y_true  float32 [8192, 2] row-major -> interleaved (survtime, censor)
//   d_in[1]: hazard  float32 [8192, 1]
// Output: d_out float32 [1]

#define COX_N   8192
#define IB      256            // i-rows per block == threads per block
#define NBJ     4              // j-chunks
#define JC      (COX_N / NBJ)  // 2048 j per chunk

// Scratch: __device__ globals (no allocation allowed anywhere).
__device__ float2 g_te[COX_N];            // {t_j, exp(theta_j)}
__device__ float  g_rpart[NBJ * COX_N];   // partial risk sums per j-chunk

// ---------------------------------------------------------------------------
// Kernel 1: pack {t, exp(theta)} as float2 for single-LDS.64 inner-loop reads.
// ---------------------------------------------------------------------------
__global__ void cox_prep_kernel(const float* __restrict__ y_true,
                                const float* __restrict__ hazard) {
    int j = blockIdx.x * blockDim.x + threadIdx.x;
    if (j < COX_N) {
        g_te[j] = make_float2(y_true[2 * j], expf(hazard[j]));
    }
}

// ---------------------------------------------------------------------------
// Kernel 2: partial risk sums. Grid = (COX_N/IB, NBJ).
// Block (bi, cj): stage j-chunk cj (16KB) in shared, every thread owns one i
// and scans the whole chunk (broadcast LDS -> conflict-free).
// ---------------------------------------------------------------------------
__global__ __launch_bounds__(IB) void cox_risk_kernel(const float* __restrict__ y_true) {
    __shared__ float2 sh[JC];

    const int cj   = blockIdx.y;
    const int base = cj * JC;

    // Coalesced global->shared staging (float2 = 8B per thread per step).
    for (int k = threadIdx.x; k < JC; k += IB) {
        sh[k] = g_te[base + k];
    }
    __syncthreads();

    const int   i  = blockIdx.x * IB + threadIdx.x;
    const float ti = y_true[2 * i];

    // 4 independent accumulators to hide LDS latency / widen ILP.
    float s0 = 0.f, s1 = 0.f, s2 = 0.f, s3 = 0.f;
    #pragma unroll 4
    for (int k = 0; k < JC; k += 4) {
        float2 a = sh[k + 0];
        float2 b = sh[k + 1];
        float2 c = sh[k + 2];
        float2 d = sh[k + 3];
        s0 += (a.x >= ti) ? a.y : 0.0f;
        s1 += (b.x >= ti) ? b.y : 0.0f;
        s2 += (c.x >= ti) ? c.y : 0.0f;
        s3 += (d.x >= ti) ? d.y : 0.0f;
    }

    g_rpart[cj * COX_N + i] = (s0 + s1) + (s2 + s3);
}

// ---------------------------------------------------------------------------
// Kernel 3: combine partials (fixed order -> deterministic), final reduction.
// Single block, 1024 threads, fixed-tree shared reduce.
// ---------------------------------------------------------------------------
__global__ __launch_bounds__(1024) void cox_loss_kernel(const float* __restrict__ y_true,
                                                        const float* __restrict__ hazard,
                                                        float* __restrict__ out) {
    __shared__ float red[1024];
    const int tid = threadIdx.x;

    float acc = 0.0f;
    for (int i = tid; i < COX_N; i += 1024) {
        float risk = ((g_rpart[0 * COX_N + i] + g_rpart[1 * COX_N + i]) +
                      (g_rpart[2 * COX_N + i] + g_rpart[3 * COX_N + i]));
        float cen  = y_true[2 * i + 1];
        float c    = (cen != 0.0f) ? 1.0f : 0.0f;
        acc += (hazard[i] - logf(risk)) * c;
    }
    red[tid] = acc;
    __syncthreads();

    #pragma unroll
    for (int s = 512; s > 0; s >>= 1) {
        if (tid < s) red[tid] += red[tid + s];
        __syncthreads();
    }
    if (tid == 0) {
        out[0] = -red[0] / (float)COX_N;
    }
}

// ---------------------------------------------------------------------------
extern "C" void kernel_launch(void* const* d_in, const int* in_sizes, int n_in,
                              void* d_out, int out_size) {
    // metadata order: y_true (2N floats), hazard_pred (N floats).
    const float* y_true = (const float*)d_in[0];
    const float* hazard = (const float*)d_in[1];
    // Defensive: if sizes indicate swapped order, swap.
    if (n_in >= 2 && in_sizes[0] < in_sizes[1]) {
        y_true = (const float*)d_in[1];
        hazard = (const float*)d_in[0];
    }
    float* out = (float*)d_out;

    cox_prep_kernel<<<(COX_N + 511) / 512, 512>>>(y_true, hazard);

    dim3 grid(COX_N / IB, NBJ);
    cox_risk_kernel<<<grid, IB>>>(y_true);

    cox_loss_kernel<<<1, 1024>>>(y_true, hazard, out);
}

// round 2
// speedup vs baseline: 1.2464x; 1.2464x over previous
#include <cuda_runtime.h>
#include <math.h>

// Cox partial-likelihood loss, N = 8192.
//   risk_sum[i] = sum_j exp(theta_j) * (t_j >= t_i)
//   loss = -(1/N) * sum_i (theta_i - log(risk_sum[i])) * censor_i
//
// Inputs (metadata order):
//   d_in[0]: y_true  float32 [8192, 2] interleaved (survtime, censor)
//   d_in[1]: hazard  float32 [8192]
// Output: d_out float32 [1]
//
// Structure (2 launches, both graph-capturable, no allocations):
//   K1 cox_risk_fused: grid (16 i-tiles, 16 j-chunks), 256 thr, 2 i/thread.
//      Fuses exp(theta) into the shared staging. Writes partial risk sums.
//   K2 cox_loss_final: 8 blocks x 1024 thr combine partials + log + reduce;
//      last block (atomic counter) folds 8 block sums in fixed order.

#define COX_N   8192
#define IB      256                 // threads per risk block
#define IPT     2                   // i per thread
#define IBLK    (IB * IPT)          // 512 i per block
#define GX      (COX_N / IBLK)      // 16 i-tiles
#define NBJ     16                  // j-chunks
#define JC      (COX_N / NBJ)       // 512 j per chunk

// Scratch: __device__ globals only (allocation is forbidden).
__device__ float g_rpart[NBJ * COX_N];  // partial risk sums
__device__ float g_bsum[8];             // per-block loss partials
__device__ int   g_count = 0;           // last-block counter (self-resetting)

// ---------------------------------------------------------------------------
// K1: fused prep + partial risk sums.
// ---------------------------------------------------------------------------
__global__ __launch_bounds__(IB) void cox_risk_fused(const float* __restrict__ y_true,
                                                     const float* __restrict__ hazard) {
    __shared__ float2 sh[JC];   // {t_j, exp(theta_j)} for this j-chunk (4KB)

    const int cj   = blockIdx.y;
    const int base = cj * JC;

    // Stage chunk; compute exp(theta) on the fly (2 expf per thread).
    for (int k = threadIdx.x; k < JC; k += IB) {
        sh[k] = make_float2(y_true[2 * (base + k)], expf(hazard[base + k]));
    }
    __syncthreads();

    const int   i0 = blockIdx.x * IBLK + threadIdx.x;
    const int   i1 = i0 + IB;
    const float t0 = y_true[2 * i0];
    const float t1 = y_true[2 * i1];

    // 4 independent accumulators; each LDS.64 feeds two i's.
    float s00 = 0.f, s01 = 0.f, s10 = 0.f, s11 = 0.f;
    #pragma unroll 4
    for (int k = 0; k < JC; k += 2) {
        float2 a = sh[k];
        float2 b = sh[k + 1];
        if (a.x >= t0) s00 += a.y;
        if (a.x >= t1) s01 += a.y;
        if (b.x >= t0) s10 += b.y;
        if (b.x >= t1) s11 += b.y;
    }

    g_rpart[cj * COX_N + i0] = s00 + s10;
    g_rpart[cj * COX_N + i1] = s01 + s11;
}

// ---------------------------------------------------------------------------
// K2: combine partials, log, censor-masked mean. 8 blocks x 1024 threads.
// Last block (via counter) folds the 8 block sums in fixed order -> bitwise
// deterministic output; counter resets to 0 for graph replay.
// ---------------------------------------------------------------------------
__global__ __launch_bounds__(1024) void cox_loss_final(const float* __restrict__ y_true,
                                                       const float* __restrict__ hazard,
                                                       float* __restrict__ out) {
    __shared__ float red[1024];
    const int tid = threadIdx.x;
    const int i   = blockIdx.x * 1024 + tid;

    float risk = 0.0f;
    #pragma unroll
    for (int c = 0; c < NBJ; c++) {
        risk += g_rpart[c * COX_N + i];   // fixed order -> deterministic
    }

    float cen = y_true[2 * i + 1];
    float acc = (cen != 0.0f) ? (hazard[i] - logf(risk)) : 0.0f;

    red[tid] = acc;
    __syncthreads();
    #pragma unroll
    for (int s = 512; s > 0; s >>= 1) {
        if (tid < s) red[tid] += red[tid + s];
        __syncthreads();
    }

    if (tid == 0) {
        g_bsum[blockIdx.x] = red[0];
        __threadfence();
        int prev = atomicAdd(&g_count, 1);
        if (prev == (int)gridDim.x - 1) {
            __threadfence();
            float tot = 0.0f;
            #pragma unroll
            for (int b = 0; b < 8; b++) tot += g_bsum[b];   // fixed order
            out[0]  = -tot / (float)COX_N;
            g_count = 0;   // reset for next graph replay
        }
    }
}

// ---------------------------------------------------------------------------
extern "C" void kernel_launch(void* const* d_in, const int* in_sizes, int n_in,
                              void* d_out, int out_size) {
    const float* y_true = (const float*)d_in[0];
    const float* hazard = (const float*)d_in[1];
    if (n_in >= 2 && in_sizes[0] < in_sizes[1]) {   // defensive order check
        y_true = (const float*)d_in[1];
        hazard = (const float*)d_in[0];
    }
    float* out = (float*)d_out;

    dim3 grid(GX, NBJ);
    cox_risk_fused<<<grid, IB>>>(y_true, hazard);
    cox_loss_final<<<8, 1024>>>(y_true, hazard, out);
}